// round 1
// baseline (speedup 1.0000x reference)
#include <cuda_runtime.h>
#include <math.h>

#define NN 50000
#define EE 800000
#define RR 2000
#define FF 128
#define FDD 384
#define PP 64

// ---------------- scratch (device globals; no allocation allowed) ----------
__device__ int   g_deg[NN];
__device__ int   g_rowptr[NN + 1];
__device__ int   g_pos[NN];
__device__ int   g_bsum[64];
__device__ int   g_srcS[EE];
__device__ int   g_relS[EE];
__device__ float g_rhat[RR * FF];
__device__ float g_sc[4 * RR];
__device__ float g_outE[(size_t)NN * FDD];
__device__ float g_outR[(size_t)NN * FDD];
__device__ float g_att[(size_t)NN * PP];
__device__ float g_pf[(size_t)NN * FDD];
__device__ float g_phN[PP * FDD];   // l2-normalized proxy rows (current dual)

// ---------------- helpers ---------------------------------------------------
__device__ __forceinline__ float warpSum(float v) {
#pragma unroll
    for (int o = 16; o; o >>= 1) v += __shfl_xor_sync(0xffffffffu, v, o);
    return v;
}
__device__ __forceinline__ float warpMax(float v) {
#pragma unroll
    for (int o = 16; o; o >>= 1) v = fmaxf(v, __shfl_xor_sync(0xffffffffu, v, o));
    return v;
}

// ---------------- CSR build -------------------------------------------------
__global__ void k_zero() {
    int i = blockIdx.x * blockDim.x + threadIdx.x;
    if (i < NN) g_deg[i] = 0;
}
__global__ void k_count(const int* __restrict__ dst) {
    int i = blockIdx.x * blockDim.x + threadIdx.x;
    if (i < EE) atomicAdd(&g_deg[dst[i]], 1);
}
__global__ void k_scan1() {
    __shared__ int s[1024];
    int i = blockIdx.x * 1024 + threadIdx.x;
    int v = (i < NN) ? g_deg[i] : 0;
    s[threadIdx.x] = v;
    __syncthreads();
#pragma unroll
    for (int off = 1; off < 1024; off <<= 1) {
        int t = (threadIdx.x >= off) ? s[threadIdx.x - off] : 0;
        __syncthreads();
        s[threadIdx.x] += t;
        __syncthreads();
    }
    if (i < NN) g_rowptr[i + 1] = s[threadIdx.x];
    if (threadIdx.x == 1023) g_bsum[blockIdx.x] = s[1023];
}
__global__ void k_scan2(int nb) {
    if (threadIdx.x == 0) {
        int run = 0;
        for (int b = 0; b < nb; b++) { int t = g_bsum[b]; g_bsum[b] = run; run += t; }
    }
}
__global__ void k_scan3() {
    int i = blockIdx.x * 1024 + threadIdx.x;
    if (i < NN) {
        int incl = g_rowptr[i + 1] + g_bsum[blockIdx.x];
        g_rowptr[i + 1] = incl;
        g_pos[i] = incl - g_deg[i];
    }
    if (i == 0) g_rowptr[0] = 0;
}
__global__ void k_fill(const int* __restrict__ src, const int* __restrict__ dst,
                       const int* __restrict__ rel) {
    int i = blockIdx.x * blockDim.x + threadIdx.x;
    if (i < EE) {
        int p = atomicAdd(&g_pos[dst[i]], 1);
        g_srcS[p] = src[i];
        g_relS[p] = rel[i];
    }
}

// ---------------- per-relation precompute ----------------------------------
__global__ void k_rhat(const float* __restrict__ rel_emb) {
    __shared__ float red[4];
    int r = blockIdx.x, t = threadIdx.x;
    float v = rel_emb[r * FF + t];
    float ss = warpSum(v * v);
    if ((t & 31) == 0) red[t >> 5] = ss;
    __syncthreads();
    float tot = red[0] + red[1] + red[2] + red[3];
    float invn = 1.0f / fmaxf(sqrtf(tot), 1e-12f);
    g_rhat[r * FF + t] = v * invn;
}
// sc[t][r] = dot(rhat[r], attn[t]); t = dual*2 + layer
__global__ void k_scores(const float* __restrict__ ae, const float* __restrict__ ar) {
    int w = (blockIdx.x * blockDim.x + threadIdx.x) >> 5;
    int lane = threadIdx.x & 31;
    if (w >= 4 * RR) return;
    int t = w / RR, r = w % RR;
    const float* attn = ((t < 2) ? ae : ar) + (t & 1) * FF;
    float4 u = *(const float4*)&g_rhat[r * FF + lane * 4];
    float4 a = *(const float4*)&attn[lane * 4];
    float d = u.x * a.x + u.y * a.y + u.z * a.z + u.w * a.w;
    d = warpSum(d);
    if (lane == 0) g_sc[t * RR + r] = d;
}

// ---------------- initial features (segment mean -> tanh) -------------------
__global__ void k_init(const float* __restrict__ ent, const float* __restrict__ rel) {
    int w = (blockIdx.x * blockDim.x + threadIdx.x) >> 5;
    int lane = threadIdx.x & 31;
    if (w >= NN) return;
    int b = g_rowptr[w], e = g_rowptr[w + 1];
    float4 aE = make_float4(0, 0, 0, 0), aR = make_float4(0, 0, 0, 0);
    for (int i = b; i < e; i++) {
        int s = g_srcS[i], r = g_relS[i];
        float4 he = *(const float4*)&ent[(size_t)s * FF + lane * 4];
        float4 hr = *(const float4*)&rel[(size_t)r * FF + lane * 4];
        aE.x += he.x; aE.y += he.y; aE.z += he.z; aE.w += he.w;
        aR.x += hr.x; aR.y += hr.y; aR.z += hr.z; aR.w += hr.w;
    }
    float inv = 1.0f / fmaxf((float)(e - b), 1.0f);
    float4 oE = make_float4(tanhf(aE.x * inv), tanhf(aE.y * inv), tanhf(aE.z * inv), tanhf(aE.w * inv));
    float4 oR = make_float4(tanhf(aR.x * inv), tanhf(aR.y * inv), tanhf(aR.z * inv), tanhf(aR.w * inv));
    *(float4*)&g_outE[(size_t)w * FDD + lane * 4] = oE;
    *(float4*)&g_outR[(size_t)w * FDD + lane * 4] = oR;
}

// ---------------- one GNN layer: Householder + edge softmax + agg + tanh ----
__global__ void k_agg(int dualSel, int layer) {
    int w = (blockIdx.x * blockDim.x + threadIdx.x) >> 5;
    int lane = threadIdx.x & 31;
    if (w >= NN) return;
    float* base = dualSel ? g_outR : g_outE;
    const float* fin = base + layer * FF;
    float* fout = base + (layer + 1) * FF;
    const float* sc = g_sc + (dualSel * 2 + layer) * RR;
    int b = g_rowptr[w], e = g_rowptr[w + 1];
    // pass 1: segment max of score
    float m = -1e30f;
    for (int i = b + lane; i < e; i += 32) m = fmaxf(m, sc[g_relS[i]]);
    m = warpMax(m);
    // pass 2: weighted Householder-reflected aggregation
    float4 acc = make_float4(0, 0, 0, 0);
    float ws = 0.0f;
    for (int i = b; i < e; i++) {
        int s = g_srcS[i], r = g_relS[i];
        float4 h = *(const float4*)&fin[(size_t)s * FDD + lane * 4];
        float4 u = *(const float4*)&g_rhat[(size_t)r * FF + lane * 4];
        float d = h.x * u.x + h.y * u.y + h.z * u.z + h.w * u.w;
        d = warpSum(d);
        float wgt = __expf(sc[r] - m);
        ws += wgt;
        float c = 2.0f * d * wgt;
        acc.x += wgt * h.x - c * u.x;
        acc.y += wgt * h.y - c * u.y;
        acc.z += wgt * h.z - c * u.z;
        acc.w += wgt * h.w - c * u.w;
    }
    float inv = (e > b) ? (1.0f / ws) : 0.0f;
    float4 o = make_float4(tanhf(acc.x * inv), tanhf(acc.y * inv), tanhf(acc.z * inv), tanhf(acc.w * inv));
    *(float4*)&fout[(size_t)w * FDD + lane * 4] = o;
}

// ---------------- normalized proxy -----------------------------------------
__global__ void k_phN(const float* __restrict__ proxy) {
    __shared__ float red[4];
    int p = blockIdx.x, t = threadIdx.x;
    float v0 = proxy[p * FDD + t];
    float v1 = proxy[p * FDD + 128 + t];
    float v2 = proxy[p * FDD + 256 + t];
    float ss = warpSum(v0 * v0 + v1 * v1 + v2 * v2);
    if ((t & 31) == 0) red[t >> 5] = ss;
    __syncthreads();
    float tot = red[0] + red[1] + red[2] + red[3];
    float invn = 1.0f / fmaxf(sqrtf(tot), 1e-12f);
    g_phN[p * FDD + t] = v0 * invn;
    g_phN[p * FDD + 128 + t] = v1 * invn;
    g_phN[p * FDD + 256 + t] = v2 * invn;
}

// ---------------- proxy attention (logits + softmax), 4 rows per warp -------
__global__ void k_logits(int dualSel) {
    __shared__ float so[8][4][FDD];          // 48 KB
    int warp = threadIdx.x >> 5, lane = threadIdx.x & 31;
    int n0 = (blockIdx.x * 8 + warp) * 4;
    const float* Of = dualSel ? g_outR : g_outE;
    float invn[4];
#pragma unroll
    for (int rr = 0; rr < 4; rr++) {
        int n = n0 + rr;
        float ss = 0.0f;
        if (n < NN) {
#pragma unroll
            for (int c = 0; c < 3; c++) {
                float4 v = *(const float4*)&Of[(size_t)n * FDD + c * 128 + lane * 4];
                *(float4*)&so[warp][rr][c * 128 + lane * 4] = v;
                ss += v.x * v.x + v.y * v.y + v.z * v.z + v.w * v.w;
            }
        }
        ss = warpSum(ss);
        invn[rr] = 1.0f / fmaxf(sqrtf(ss), 1e-12f);
    }
    __syncwarp();
    float l[4][2];
#pragma unroll
    for (int rr = 0; rr < 4; rr++) { l[rr][0] = 0.0f; l[rr][1] = 0.0f; }
    for (int j = 0; j < FDD; j += 4) {
        float4 q0 = *(const float4*)&g_phN[lane * FDD + j];
        float4 q1 = *(const float4*)&g_phN[(lane + 32) * FDD + j];
#pragma unroll
        for (int rr = 0; rr < 4; rr++) {
            float4 ov = *(const float4*)&so[warp][rr][j];
            l[rr][0] += ov.x * q0.x + ov.y * q0.y + ov.z * q0.z + ov.w * q0.w;
            l[rr][1] += ov.x * q1.x + ov.y * q1.y + ov.z * q1.z + ov.w * q1.w;
        }
    }
#pragma unroll
    for (int rr = 0; rr < 4; rr++) {
        float a0 = l[rr][0] * invn[rr], a1 = l[rr][1] * invn[rr];
        float m = warpMax(fmaxf(a0, a1));
        float w0 = __expf(a0 - m), w1 = __expf(a1 - m);
        float s = warpSum(w0 + w1);
        float is = 1.0f / s;
        int n = n0 + rr;
        if (n < NN) {
            g_att[(size_t)n * PP + lane] = w0 * is;
            g_att[(size_t)n * PP + 32 + lane] = w1 * is;
        }
    }
}

// ---------------- proxy feature pf = outputs - att @ proxy, 4 rows/warp -----
__global__ void k_pf(const float* __restrict__ proxy, int dualSel) {
    int warp = threadIdx.x >> 5, lane = threadIdx.x & 31;
    int n0 = (blockIdx.x * 8 + warp) * 4;
    const float* Of = dualSel ? g_outR : g_outE;
    float a[4][2];
    float4 acc[4][3];
#pragma unroll
    for (int rr = 0; rr < 4; rr++) {
        int n = n0 + rr;
        if (n < NN) {
            a[rr][0] = g_att[(size_t)n * PP + lane];
            a[rr][1] = g_att[(size_t)n * PP + 32 + lane];
#pragma unroll
            for (int c = 0; c < 3; c++)
                acc[rr][c] = *(const float4*)&Of[(size_t)n * FDD + c * 128 + lane * 4];
        } else {
            a[rr][0] = a[rr][1] = 0.0f;
#pragma unroll
            for (int c = 0; c < 3; c++) acc[rr][c] = make_float4(0, 0, 0, 0);
        }
    }
#pragma unroll 16
    for (int p = 0; p < PP; p++) {
        const float* pr = proxy + p * FDD;
        float4 q0 = *(const float4*)&pr[lane * 4];
        float4 q1 = *(const float4*)&pr[128 + lane * 4];
        float4 q2 = *(const float4*)&pr[256 + lane * 4];
#pragma unroll
        for (int rr = 0; rr < 4; rr++) {
            float src = (p < 32) ? a[rr][0] : a[rr][1];
            float av = __shfl_sync(0xffffffffu, src, p & 31);
            acc[rr][0].x -= av * q0.x; acc[rr][0].y -= av * q0.y;
            acc[rr][0].z -= av * q0.z; acc[rr][0].w -= av * q0.w;
            acc[rr][1].x -= av * q1.x; acc[rr][1].y -= av * q1.y;
            acc[rr][1].z -= av * q1.z; acc[rr][1].w -= av * q1.w;
            acc[rr][2].x -= av * q2.x; acc[rr][2].y -= av * q2.y;
            acc[rr][2].z -= av * q2.z; acc[rr][2].w -= av * q2.w;
        }
    }
#pragma unroll
    for (int rr = 0; rr < 4; rr++) {
        int n = n0 + rr;
        if (n < NN) {
#pragma unroll
            for (int c = 0; c < 3; c++)
                *(float4*)&g_pf[(size_t)n * FDD + c * 128 + lane * 4] = acc[rr][c];
        }
    }
}

// ---------------- gate GEMM + sigmoid + final blend -------------------------
__device__ __forceinline__ float gateCombine(float t, float b, float o, float p) {
    float g = 1.0f / (1.0f + __expf(-(t + b)));
    return g * o + (1.0f - g) * p;
}
__global__ void k_gemm(const float* __restrict__ B, const float* __restrict__ bias,
                       int dualSel, int dualoff, float* __restrict__ out) {
    const float* A = g_pf;
    const float* O = dualSel ? g_outR : g_outE;
    __shared__ float As[8][128];
    __shared__ float Bs[8][128];
    int tid = threadIdx.x;
    int m0 = blockIdx.x * 128, j0 = blockIdx.y * 128;
    int arow = tid >> 1, acol = (tid & 1) * 4;
    int brow = tid >> 5, bcol = (tid & 31) * 4;
    int tx = tid & 15, ty = tid >> 4;
    float acc[8][8];
#pragma unroll
    for (int i = 0; i < 8; i++)
#pragma unroll
        for (int j = 0; j < 8; j++) acc[i][j] = 0.0f;

    int gr = m0 + arow;
    float4 ra, rb;
    // fetch k-tile 0
    ra = (gr < NN) ? *(const float4*)&A[(size_t)gr * FDD + acol] : make_float4(0, 0, 0, 0);
    rb = *(const float4*)&B[(size_t)brow * FDD + j0 + bcol];

    for (int kt = 0; kt < FDD / 8; kt++) {
        As[acol + 0][arow] = ra.x;
        As[acol + 1][arow] = ra.y;
        As[acol + 2][arow] = ra.z;
        As[acol + 3][arow] = ra.w;
        *(float4*)&Bs[brow][bcol] = rb;
        __syncthreads();
        if (kt + 1 < FDD / 8) {
            int k0 = (kt + 1) * 8;
            ra = (gr < NN) ? *(const float4*)&A[(size_t)gr * FDD + k0 + acol] : make_float4(0, 0, 0, 0);
            rb = *(const float4*)&B[(size_t)(k0 + brow) * FDD + j0 + bcol];
        }
#pragma unroll
        for (int kk = 0; kk < 8; kk++) {
            float av[8], bv[8];
            *(float4*)&av[0] = *(const float4*)&As[kk][ty * 8];
            *(float4*)&av[4] = *(const float4*)&As[kk][ty * 8 + 4];
            *(float4*)&bv[0] = *(const float4*)&Bs[kk][tx * 8];
            *(float4*)&bv[4] = *(const float4*)&Bs[kk][tx * 8 + 4];
#pragma unroll
            for (int i = 0; i < 8; i++)
#pragma unroll
                for (int j = 0; j < 8; j++) acc[i][j] += av[i] * bv[j];
        }
        __syncthreads();
    }
    // epilogue: g = sigmoid(acc + bias); out = g*o + (1-g)*pf
#pragma unroll
    for (int i = 0; i < 8; i++) {
        int row = m0 + ty * 8 + i;
        if (row < NN) {
#pragma unroll
            for (int h = 0; h < 2; h++) {
                int c = j0 + tx * 8 + h * 4;
                float4 ov = *(const float4*)&O[(size_t)row * FDD + c];
                float4 pv = *(const float4*)&g_pf[(size_t)row * FDD + c];
                float4 bb = *(const float4*)&bias[c];
                float4 res;
                res.x = gateCombine(acc[i][h * 4 + 0], bb.x, ov.x, pv.x);
                res.y = gateCombine(acc[i][h * 4 + 1], bb.y, ov.y, pv.y);
                res.z = gateCombine(acc[i][h * 4 + 2], bb.z, ov.z, pv.z);
                res.w = gateCombine(acc[i][h * 4 + 3], bb.w, ov.w, pv.w);
                *(float4*)&out[(size_t)row * (2 * FDD) + dualoff + c] = res;
            }
        }
    }
}

// ---------------- launch -----------------------------------------------------
extern "C" void kernel_launch(void* const* d_in, const int* in_sizes, int n_in,
                              void* d_out, int out_size) {
    const float* ent     = (const float*)d_in[0];
    const float* rel     = (const float*)d_in[1];
    const int*   esrc    = (const int*)d_in[2];
    const int*   edst    = (const int*)d_in[3];
    const int*   erel    = (const int*)d_in[4];
    const float* attn_e  = (const float*)d_in[5];
    const float* gate_e  = (const float*)d_in[6];
    const float* proxy_e = (const float*)d_in[7];
    const float* bias_e  = (const float*)d_in[8];
    const float* attn_r  = (const float*)d_in[9];
    const float* gate_r  = (const float*)d_in[10];
    const float* proxy_r = (const float*)d_in[11];
    const float* bias_r  = (const float*)d_in[12];
    float* out = (float*)d_out;

    const int nb = (NN + 1023) / 1024;          // 49
    // CSR build
    k_zero<<<(NN + 255) / 256, 256>>>();
    k_count<<<(EE + 255) / 256, 256>>>(edst);
    k_scan1<<<nb, 1024>>>();
    k_scan2<<<1, 32>>>(nb);
    k_scan3<<<nb, 1024>>>();
    k_fill<<<(EE + 255) / 256, 256>>>(esrc, edst, erel);
    // per-relation precompute
    k_rhat<<<RR, 128>>>(rel);
    k_scores<<<(4 * RR * 32 + 255) / 256, 256>>>(attn_e, attn_r);
    // initial features (both duals share graph & inputs)
    k_init<<<(NN + 7) / 8, 256>>>(ent, rel);
    // 2 layers x 2 duals of message passing
    k_agg<<<(NN + 7) / 8, 256>>>(0, 0);
    k_agg<<<(NN + 7) / 8, 256>>>(0, 1);
    k_agg<<<(NN + 7) / 8, 256>>>(1, 0);
    k_agg<<<(NN + 7) / 8, 256>>>(1, 1);
    // epilogue: dual E
    const int nwb = (NN / 4 + 7) / 8;           // 1563 blocks of 8 warps x 4 rows
    k_phN<<<PP, 128>>>(proxy_e);
    k_logits<<<nwb, 256>>>(0);
    k_pf<<<nwb, 256>>>(proxy_e, 0);
    k_gemm<<<dim3((NN + 127) / 128, FDD / 128), 256>>>(gate_e, bias_e, 0, 0, out);
    // epilogue: dual R
    k_phN<<<PP, 128>>>(proxy_r);
    k_logits<<<nwb, 256>>>(1);
    k_pf<<<nwb, 256>>>(proxy_r, 1);
    k_gemm<<<dim3((NN + 127) / 128, FDD / 128), 256>>>(gate_r, bias_r, 1, FDD, out);
}